// round 14
// baseline (speedup 1.0000x reference)
#include <cuda_runtime.h>

#define NUM_CAT   16
#define NUM_ATTR  144
#define NUM_NUM   128
#define N_ARY     32
#define NUM_SEG   100000
#define N_ROWS    1000000

// Scratch (device globals — no allocation allowed in kernel_launch)
__device__ __align__(16) float g_agg[NUM_SEG * N_ARY];   // 12.8 MB, L2-resident; slot = output rank
__device__ int   g_catidx[N_ROWS];                        // compact per-row segment id
__device__ __align__(16) float g_conf[N_ARY];             // conf by output rank
__device__ int   g_cols_rank[N_ARY];                      // rank k -> numeric col (0..127)
__device__ int   g_catcol;

// ---------------------------------------------------------------------------
// Kernel 0a: setup, 1 warp. Rank-based top-k: ONE all-pairs pass of
// independent shfl broadcasts (pipelined). Rank == agg slot == output column.
// ---------------------------------------------------------------------------
__global__ void k_setup(const float* __restrict__ cat_mask,
                        const float* __restrict__ num_mask) {
    const unsigned FULL = 0xffffffffu;
    int lane = threadIdx.x;

    // --- categorical softmax + top-1 (16 values across lanes 0..15) ---
    float cv = (lane < NUM_CAT) ? cat_mask[lane] : -1e30f;
    float cm = cv;
    for (int o = 16; o; o >>= 1) cm = fmaxf(cm, __shfl_xor_sync(FULL, cm, o));
    float ce = (lane < NUM_CAT) ? expf(cv - cm) : 0.f;
    float cs = ce;
    for (int o = 16; o; o >>= 1) cs += __shfl_xor_sync(FULL, cs, o);
    float cp = ce / cs;
    float bv = cp; int bi = lane;
    for (int o = 16; o; o >>= 1) {               // argmax, first-index tie-break
        float ov = __shfl_xor_sync(FULL, bv, o);
        int   oi = __shfl_xor_sync(FULL, bi, o);
        if (ov > bv || (ov == bv && oi < bi)) { bv = ov; bi = oi; }
    }
    float top_cat_val = bv;
    if (lane == 0) g_catcol = bi;

    // --- numeric softmax (lane holds cols lane, lane+32, lane+64, lane+96) ---
    float nv[4];
#pragma unroll
    for (int j = 0; j < 4; j++) nv[j] = num_mask[lane + 32 * j];
    float nm = fmaxf(fmaxf(nv[0], nv[1]), fmaxf(nv[2], nv[3]));
    for (int o = 16; o; o >>= 1) nm = fmaxf(nm, __shfl_xor_sync(FULL, nm, o));
    float ns = 0.f;
#pragma unroll
    for (int j = 0; j < 4; j++) { nv[j] = expf(nv[j] - nm); ns += nv[j]; }
    for (int o = 16; o; o >>= 1) ns += __shfl_xor_sync(FULL, ns, o);
    float inv = 1.f / ns;
#pragma unroll
    for (int j = 0; j < 4; j++) nv[j] *= inv;

    // --- descending rank of each value (stable: smaller col wins tie) ---
    int rk[4] = {0, 0, 0, 0};
    for (int s = 0; s < 32; s++) {
#pragma unroll
        for (int j2 = 0; j2 < 4; j2++) {
            float ov = __shfl_sync(FULL, nv[j2], s);
            int   oc = s + 32 * j2;
#pragma unroll
            for (int j = 0; j < 4; j++) {
                int mc = lane + 32 * j;
                rk[j] += (ov > nv[j]) || (ov == nv[j] && oc < mc);
            }
        }
    }

#pragma unroll
    for (int j = 0; j < 4; j++) {
        if (rk[j] < N_ARY) {                      // this value is output rank rk[j]
            g_conf[rk[j]]      = 0.5f * (nv[j] + top_cat_val);
            g_cols_rank[rk[j]] = lane + 32 * j;   // numeric-relative col
        }
    }
}

// ---------------------------------------------------------------------------
// Kernel 0b: zero agg. Coalesced (j*blockDim stride), 4 float4/thread.
// ---------------------------------------------------------------------------
__global__ void k_zero() {
    const int total = NUM_SEG * N_ARY / 4;            // 800,000 float4
    int base = blockIdx.x * (256 * 4) + threadIdx.x;
    float4 z = make_float4(0.f, 0.f, 0.f, 0.f);
#pragma unroll
    for (int j = 0; j < 4; j++) {
        int i = base + j * 256;
        if (i < total) reinterpret_cast<float4*>(g_agg)[i] = z;
    }
}

// ---------------------------------------------------------------------------
// Kernel 1: scatter-add. Warp handles 8 rows via cp.async (LDGSTS):
//   8 async global->shared row copies in flight per warp (no register
//   round-trip, no STS issue slots, regs ~30) + 2 front-batched idx loads.
//   Then each lane serves 2 (row, quad) pairs: 4 LDS + ONE
//   red.global.add.v4.f32 each into the L2-resident agg table.
// ---------------------------------------------------------------------------
__global__ void k_scatter(const float* __restrict__ inputs,
                          const int* __restrict__ idx_inputs) {
    __shared__ __align__(16) float s_row[8][8][132];   // 8 warps x 8 rows, +4 pad (33.8KB)
    __shared__ int s_cols[N_ARY];
    __shared__ int s_catcol;
    if (threadIdx.x < N_ARY)  s_cols[threadIdx.x] = g_cols_rank[threadIdx.x];
    if (threadIdx.x == N_ARY) s_catcol = g_catcol;
    __syncthreads();

    int warp = threadIdx.x >> 5;
    int lane = threadIdx.x & 31;
    int base = (blockIdx.x * 8 + warp) * 8;            // 8 rows per warp

    int jr = lane >> 3;                                // 0..3
    int g  = lane & 7;                                 // rank-quad owner
    int r0 = base + jr;                                // pair t=0 row
    int r1 = base + 4 + jr;                            // pair t=1 row

    // ---- front-batch idx loads (8-lane broadcast each) ----
    int seg0 = __ldg(&idx_inputs[(size_t)r0 * NUM_CAT + s_catcol]);
    int seg1 = __ldg(&idx_inputs[(size_t)r1 * NUM_CAT + s_catcol]);

    // ---- 8 async row copies: global -> shared, 16B per lane per row ----
#pragma unroll
    for (int q = 0; q < 8; q++) {
        const float4* src = reinterpret_cast<const float4*>(
            inputs + (size_t)(base + q) * NUM_ATTR + NUM_CAT) + lane;
        unsigned saddr = (unsigned)__cvta_generic_to_shared(&s_row[warp][q][lane * 4]);
        asm volatile("cp.async.cg.shared.global [%0], [%1], 16;"
                     :: "r"(saddr), "l"(src) : "memory");
    }
    asm volatile("cp.async.commit_group;" ::: "memory");
    asm volatile("cp.async.wait_group 0;" ::: "memory");
    __syncwarp();

    seg0 = min(max(seg0, 0), NUM_SEG - 1);             // defensive: never OOB
    seg1 = min(max(seg1, 0), NUM_SEG - 1);
    if (g == 0) {
        g_catidx[r0] = seg0;                           // compact copies for gather
        g_catidx[r1] = seg1;
    }

    int c0 = s_cols[4 * g + 0];
    int c1 = s_cols[4 * g + 1];
    int c2 = s_cols[4 * g + 2];
    int c3 = s_cols[4 * g + 3];

    // ---- pair t=0: row jr ----
    {
        const float* srow = s_row[warp][jr];
        float v0 = srow[c0], v1 = srow[c1], v2 = srow[c2], v3 = srow[c3];
        float* dst = &g_agg[(size_t)seg0 * N_ARY + 4 * g];
        asm volatile("red.global.add.v4.f32 [%0], {%1,%2,%3,%4};"
                     :: "l"(dst), "f"(v0), "f"(v1), "f"(v2), "f"(v3)
                     : "memory");
    }
    // ---- pair t=1: row 4+jr ----
    {
        const float* srow = s_row[warp][4 + jr];
        float v0 = srow[c0], v1 = srow[c1], v2 = srow[c2], v3 = srow[c3];
        float* dst = &g_agg[(size_t)seg1 * N_ARY + 4 * g];
        asm volatile("red.global.add.v4.f32 [%0], {%1,%2,%3,%4};"
                     :: "l"(dst), "f"(v0), "f"(v1), "f"(v2), "f"(v3)
                     : "memory");
    }
}

// ---------------------------------------------------------------------------
// Kernel 2: gather + scale, float4 path (agg slot == output rank). 8 lanes x
// float4 per row, 16 rows/warp front-batched. 1 LDG.128 + 1 STG.128 per row.
// ---------------------------------------------------------------------------
__global__ void k_gather(float* __restrict__ out) {
    __shared__ float4 s_conf4[8];
    if (threadIdx.x < 8)
        s_conf4[threadIdx.x] = reinterpret_cast<const float4*>(g_conf)[threadIdx.x];
    __syncthreads();

    int warp = threadIdx.x >> 5;
    int lane = threadIdx.x & 31;
    int q  = lane & 7;                                 // float4 index within row
    int jr = lane >> 3;                                // row within step-quad
    float4 conf4 = s_conf4[q];

    int base = (blockIdx.x * 8 + warp) * 16;           // 16 rows per warp
    if (base >= N_ROWS) return;                        // tail warps

    int segs[4];
#pragma unroll
    for (int s = 0; s < 4; s++)
        segs[s] = g_catidx[base + s * 4 + jr];         // 8-lane broadcast loads

    float4 v[4];
#pragma unroll
    for (int s = 0; s < 4; s++)
        v[s] = reinterpret_cast<const float4*>(g_agg)[(size_t)segs[s] * 8 + q];

#pragma unroll
    for (int s = 0; s < 4; s++) {
        int r = base + s * 4 + jr;
        float4 o = make_float4(v[s].x * conf4.x, v[s].y * conf4.y,
                               v[s].z * conf4.z, v[s].w * conf4.w);
        reinterpret_cast<float4*>(out)[(size_t)r * 8 + q] = o;
    }
}

// ---------------------------------------------------------------------------
extern "C" void kernel_launch(void* const* d_in, const int* in_sizes, int n_in,
                              void* d_out, int out_size) {
    const float* inputs     = (const float*)d_in[0];
    const int*   idx_inputs = (const int*)d_in[1];     // int32 (JAX x64 off)
    const float* cat_mask   = (const float*)d_in[2];
    const float* num_mask   = (const float*)d_in[3];
    float*       out        = (float*)d_out;

    k_setup<<<1, 32>>>(cat_mask, num_mask);
    k_zero<<<782, 256>>>();
    k_scatter<<<15625, 256>>>(inputs, idx_inputs);      // 8 warps x 8 rows, cp.async
    k_gather<<<7813, 256>>>(out);                       // 8 warps x 16 rows, float4
}

// round 15
// speedup vs baseline: 1.1193x; 1.1193x over previous
#include <cuda_runtime.h>

#define NUM_CAT   16
#define NUM_ATTR  144
#define NUM_NUM   128
#define N_ARY     32
#define NUM_SEG   100000
#define N_ROWS    1000000

#define ZB 782                     // zero blocks: 782*256*4 = 800,768 >= 800,000 float4

// Scratch (device globals — no allocation allowed in kernel_launch)
__device__ __align__(16) float g_agg[NUM_SEG * N_ARY];   // 12.8 MB, L2-resident; slot = output rank
__device__ int   g_catidx[N_ROWS];                        // compact per-row segment id
__device__ __align__(16) float g_conf[N_ARY];             // conf by output rank
__device__ int   g_cols_rank[N_ARY];                      // rank k -> numeric col (0..127)
__device__ int   g_catcol;

// ---------------------------------------------------------------------------
// Kernel 0: fused init. Blocks 0..781 zero agg (coalesced, 4 float4/thread);
// block 782 / warp 0 runs the rank-based softmax/top-k setup (~1.5us, fully
// pipelined all-pairs shfl broadcasts; rank == agg slot == output column).
// ---------------------------------------------------------------------------
__global__ void k_init(const float* __restrict__ cat_mask,
                       const float* __restrict__ num_mask) {
    const unsigned FULL = 0xffffffffu;

    if (blockIdx.x < ZB) {                             // ---- zero pass ----
        const int total = NUM_SEG * N_ARY / 4;         // 800,000 float4
        int base = blockIdx.x * (256 * 4) + threadIdx.x;
        float4 z = make_float4(0.f, 0.f, 0.f, 0.f);
#pragma unroll
        for (int j = 0; j < 4; j++) {
            int i = base + j * 256;
            if (i < total) reinterpret_cast<float4*>(g_agg)[i] = z;
        }
        return;
    }
    if (threadIdx.x >= 32) return;                     // ---- setup warp ----
    int lane = threadIdx.x;

    // --- categorical softmax + top-1 (16 values across lanes 0..15) ---
    float cv = (lane < NUM_CAT) ? cat_mask[lane] : -1e30f;
    float cm = cv;
    for (int o = 16; o; o >>= 1) cm = fmaxf(cm, __shfl_xor_sync(FULL, cm, o));
    float ce = (lane < NUM_CAT) ? expf(cv - cm) : 0.f;
    float cs = ce;
    for (int o = 16; o; o >>= 1) cs += __shfl_xor_sync(FULL, cs, o);
    float cp = ce / cs;
    float bv = cp; int bi = lane;
    for (int o = 16; o; o >>= 1) {               // argmax, first-index tie-break
        float ov = __shfl_xor_sync(FULL, bv, o);
        int   oi = __shfl_xor_sync(FULL, bi, o);
        if (ov > bv || (ov == bv && oi < bi)) { bv = ov; bi = oi; }
    }
    float top_cat_val = bv;
    if (lane == 0) g_catcol = bi;

    // --- numeric softmax (lane holds cols lane, lane+32, lane+64, lane+96) ---
    float nv[4];
#pragma unroll
    for (int j = 0; j < 4; j++) nv[j] = num_mask[lane + 32 * j];
    float nm = fmaxf(fmaxf(nv[0], nv[1]), fmaxf(nv[2], nv[3]));
    for (int o = 16; o; o >>= 1) nm = fmaxf(nm, __shfl_xor_sync(FULL, nm, o));
    float ns = 0.f;
#pragma unroll
    for (int j = 0; j < 4; j++) { nv[j] = expf(nv[j] - nm); ns += nv[j]; }
    for (int o = 16; o; o >>= 1) ns += __shfl_xor_sync(FULL, ns, o);
    float inv = 1.f / ns;
#pragma unroll
    for (int j = 0; j < 4; j++) nv[j] *= inv;

    // --- descending rank of each value (stable: smaller col wins tie) ---
    int rk[4] = {0, 0, 0, 0};
    for (int s = 0; s < 32; s++) {
#pragma unroll
        for (int j2 = 0; j2 < 4; j2++) {
            float ov = __shfl_sync(FULL, nv[j2], s);
            int   oc = s + 32 * j2;
#pragma unroll
            for (int j = 0; j < 4; j++) {
                int mc = lane + 32 * j;
                rk[j] += (ov > nv[j]) || (ov == nv[j] && oc < mc);
            }
        }
    }

#pragma unroll
    for (int j = 0; j < 4; j++) {
        if (rk[j] < N_ARY) {                      // this value is output rank rk[j]
            g_conf[rk[j]]      = 0.5f * (nv[j] + top_cat_val);
            g_cols_rank[rk[j]] = lane + 32 * j;   // numeric-relative col
        }
    }
}

// ---------------------------------------------------------------------------
// Kernel 1: scatter-add (R13-proven shape). Warp handles 4 rows.
//   front-batched __ldcs float4 loads (evict-first keeps agg L2-resident)
//   -> padded shared (132-float stride) -> 8 lanes/row pick ranks 4g..4g+3
//   -> ONE red.global.add.v4.f32 per lane into the L2-resident agg table.
// ---------------------------------------------------------------------------
__global__ void k_scatter(const float* __restrict__ inputs,
                          const int* __restrict__ idx_inputs) {
    __shared__ __align__(16) float s_row[8][4][132];   // 8 warps x 4 rows, +4 pad
    __shared__ int s_cols[N_ARY];
    __shared__ int s_catcol;
    if (threadIdx.x < N_ARY)  s_cols[threadIdx.x] = g_cols_rank[threadIdx.x];
    if (threadIdx.x == N_ARY) s_catcol = g_catcol;
    __syncthreads();

    int warp = threadIdx.x >> 5;
    int lane = threadIdx.x & 31;
    int base = (blockIdx.x * 8 + warp) * 4;            // 4 rows per warp

    int j = lane >> 3;                                 // row within the 4-group
    int g = lane & 7;                                  // rank-quad owner
    int r = base + j;

    // ---- front-batch all global loads (idx + 4 row quarters) ----
    int seg = __ldg(&idx_inputs[(size_t)r * NUM_CAT + s_catcol]); // 8-lane bcast
    float4 v[4];
#pragma unroll
    for (int q = 0; q < 4; q++) {
        v[q] = __ldcs(reinterpret_cast<const float4*>(
                   inputs + (size_t)(base + q) * NUM_ATTR + NUM_CAT) + lane);
    }

#pragma unroll
    for (int q = 0; q < 4; q++)
        *reinterpret_cast<float4*>(&s_row[warp][q][lane * 4]) = v[q];
    __syncwarp();

    seg = min(max(seg, 0), NUM_SEG - 1);               // defensive: never OOB
    if (g == 0) g_catidx[r] = seg;                     // compact copy for gather

    const float* srow = s_row[warp][j];
    float v0 = srow[s_cols[4 * g + 0]];
    float v1 = srow[s_cols[4 * g + 1]];
    float v2 = srow[s_cols[4 * g + 2]];
    float v3 = srow[s_cols[4 * g + 3]];

    float* dst = &g_agg[(size_t)seg * N_ARY + 4 * g];  // 16B-aligned, slot=rank
    asm volatile("red.global.add.v4.f32 [%0], {%1,%2,%3,%4};"
                 :: "l"(dst), "f"(v0), "f"(v1), "f"(v2), "f"(v3)
                 : "memory");
}

// ---------------------------------------------------------------------------
// Kernel 2: gather + scale, float4 path (agg slot == output rank). 8 lanes x
// float4 per row, 16 rows/warp front-batched. 1 LDG.128 + 1 STG.128 per row.
// ---------------------------------------------------------------------------
__global__ void k_gather(float* __restrict__ out) {
    __shared__ float4 s_conf4[8];
    if (threadIdx.x < 8)
        s_conf4[threadIdx.x] = reinterpret_cast<const float4*>(g_conf)[threadIdx.x];
    __syncthreads();

    int warp = threadIdx.x >> 5;
    int lane = threadIdx.x & 31;
    int q  = lane & 7;                                 // float4 index within row
    int jr = lane >> 3;                                // row within step-quad
    float4 conf4 = s_conf4[q];

    int base = (blockIdx.x * 8 + warp) * 16;           // 16 rows per warp
    if (base >= N_ROWS) return;                        // tail warps

    int segs[4];
#pragma unroll
    for (int s = 0; s < 4; s++)
        segs[s] = g_catidx[base + s * 4 + jr];         // 8-lane broadcast loads

    float4 v[4];
#pragma unroll
    for (int s = 0; s < 4; s++)
        v[s] = reinterpret_cast<const float4*>(g_agg)[(size_t)segs[s] * 8 + q];

#pragma unroll
    for (int s = 0; s < 4; s++) {
        int r = base + s * 4 + jr;
        float4 o = make_float4(v[s].x * conf4.x, v[s].y * conf4.y,
                               v[s].z * conf4.z, v[s].w * conf4.w);
        reinterpret_cast<float4*>(out)[(size_t)r * 8 + q] = o;
    }
}

// ---------------------------------------------------------------------------
extern "C" void kernel_launch(void* const* d_in, const int* in_sizes, int n_in,
                              void* d_out, int out_size) {
    const float* inputs     = (const float*)d_in[0];
    const int*   idx_inputs = (const int*)d_in[1];     // int32 (JAX x64 off)
    const float* cat_mask   = (const float*)d_in[2];
    const float* num_mask   = (const float*)d_in[3];
    float*       out        = (float*)d_out;

    k_init<<<ZB + 1, 256>>>(cat_mask, num_mask);        // zero + setup, one launch
    k_scatter<<<31250, 256>>>(inputs, idx_inputs);      // 8 warps x 4 rows (R13)
    k_gather<<<7813, 256>>>(out);                       // 8 warps x 16 rows, float4
}